// round 10
// baseline (speedup 1.0000x reference)
#include <cuda_runtime.h>
#include <cuda_bf16.h>
#include <math.h>
#include <stdint.h>

// Problem constants
constexpr int SEQ   = 1024;
constexpr int DM    = 1024;
constexpr int NHEAD = 16;
constexpr int HDIM  = 64;
constexpr int NB    = 4;
constexpr int MR    = NB * SEQ;

// ---------------- scratch (device globals; no allocation allowed) ----------
__device__ float g_s [(size_t)NB * NHEAD * SEQ * SEQ];   // raw scores (b,h,q,j)

__device__ __nv_bfloat16 g_yh[(size_t)MR * DM];
__device__ __nv_bfloat16 g_yl[(size_t)MR * DM];
__device__ __nv_bfloat16 g_xh[(size_t)MR * DM];
__device__ __nv_bfloat16 g_xl[(size_t)MR * DM];
__device__ __nv_bfloat16 g_qh[(size_t)MR * DM];
__device__ __nv_bfloat16 g_ql[(size_t)MR * DM];
__device__ __nv_bfloat16 g_kh[(size_t)MR * DM];
__device__ __nv_bfloat16 g_kl[(size_t)MR * DM];
__device__ __nv_bfloat16 g_vh[(size_t)MR * DM];
__device__ __nv_bfloat16 g_vl[(size_t)MR * DM];
__device__ __nv_bfloat16 g_vth[(size_t)MR * DM];   // v^T per (b,h): [b][h][d][j]
__device__ __nv_bfloat16 g_vtl[(size_t)MR * DM];
__device__ __nv_bfloat16 g_avh[(size_t)MR * DM];
__device__ __nv_bfloat16 g_avl[(size_t)MR * DM];
__device__ __nv_bfloat16 g_atth[(size_t)NHEAD * SEQ * SEQ];
__device__ __nv_bfloat16 g_attl[(size_t)NHEAD * SEQ * SEQ];
__device__ __nv_bfloat16 g_wqh[(size_t)DM * DM];
__device__ __nv_bfloat16 g_wql[(size_t)DM * DM];
__device__ __nv_bfloat16 g_wkh[(size_t)DM * DM];
__device__ __nv_bfloat16 g_wkl[(size_t)DM * DM];
__device__ __nv_bfloat16 g_wvh[(size_t)DM * DM];
__device__ __nv_bfloat16 g_wvl[(size_t)DM * DM];
__device__ __nv_bfloat16 g_woh[(size_t)DM * DM];
__device__ __nv_bfloat16 g_wol[(size_t)DM * DM];

// ===========================================================================
// helpers
// ===========================================================================
__device__ __forceinline__ uint32_t smem_u32(const void* p) {
    uint32_t r;
    asm("{ .reg .u64 t; cvta.to.shared.u64 t, %1; cvt.u32.u64 %0, t; }"
        : "=r"(r) : "l"(p));
    return r;
}
__device__ __forceinline__ void cp16(uint32_t dst, const void* src) {
    asm volatile("cp.async.cg.shared.global [%0], [%1], 16;" :: "r"(dst), "l"(src));
}
__device__ __forceinline__ void cp_commit() {
    asm volatile("cp.async.commit_group;" ::: "memory");
}
template <int N>
__device__ __forceinline__ void cp_wait() {
    asm volatile("cp.async.wait_group %0;" :: "n"(N) : "memory");
}
__device__ __forceinline__ void ldsm_x4(uint32_t* r, uint32_t addr) {
    asm volatile("ldmatrix.sync.aligned.m8n8.x4.shared.b16 {%0,%1,%2,%3}, [%4];"
        : "=r"(r[0]), "=r"(r[1]), "=r"(r[2]), "=r"(r[3]) : "r"(addr));
}
__device__ __forceinline__ void mma16816(
    float* d, const uint32_t* a, const uint32_t* b)
{
    asm volatile(
        "mma.sync.aligned.m16n8k16.row.col.f32.bf16.bf16.f32 "
        "{%0,%1,%2,%3}, {%4,%5,%6,%7}, {%8,%9}, {%0,%1,%2,%3};"
        : "+f"(d[0]), "+f"(d[1]), "+f"(d[2]), "+f"(d[3])
        : "r"(a[0]), "r"(a[1]), "r"(a[2]), "r"(a[3]), "r"(b[0]), "r"(b[1]));
}

// ===========================================================================
// combined fp32 -> bf16 hi/lo split for the 6 input tensors (1 launch)
// blockIdx.y selects segment: 0=y, 1=x (act), 2..5=weights
// ===========================================================================
__global__ __launch_bounds__(256) void split6_kernel(
    const float* __restrict__ y,  __nv_bfloat16* yh, __nv_bfloat16* yl,
    const float* __restrict__ x,  __nv_bfloat16* xh, __nv_bfloat16* xl,
    const float* __restrict__ wq, __nv_bfloat16* qh, __nv_bfloat16* ql,
    const float* __restrict__ wk, __nv_bfloat16* kh, __nv_bfloat16* kl,
    const float* __restrict__ wv, __nv_bfloat16* vh, __nv_bfloat16* vl,
    const float* __restrict__ wo, __nv_bfloat16* oh, __nv_bfloat16* ol)
{
    const int seg = blockIdx.y;
    const float* in; __nv_bfloat16 *hi, *lo; int n4;
    switch (seg) {
        case 0:  in = y;  hi = yh; lo = yl; n4 = MR * DM / 4; break;
        case 1:  in = x;  hi = xh; lo = xl; n4 = MR * DM / 4; break;
        case 2:  in = wq; hi = qh; lo = ql; n4 = DM * DM / 4; break;
        case 3:  in = wk; hi = kh; lo = kl; n4 = DM * DM / 4; break;
        case 4:  in = wv; hi = vh; lo = vl; n4 = DM * DM / 4; break;
        default: in = wo; hi = oh; lo = ol; n4 = DM * DM / 4; break;
    }
    int i = blockIdx.x * blockDim.x + threadIdx.x;
    if (i >= n4) return;
    float4 v = ((const float4*)in)[i];
    __nv_bfloat16 h0 = __float2bfloat16(v.x);
    __nv_bfloat16 h1 = __float2bfloat16(v.y);
    __nv_bfloat16 h2 = __float2bfloat16(v.z);
    __nv_bfloat16 h3 = __float2bfloat16(v.w);
    ushort4 H, L;
    H.x = __bfloat16_as_ushort(h0); H.y = __bfloat16_as_ushort(h1);
    H.z = __bfloat16_as_ushort(h2); H.w = __bfloat16_as_ushort(h3);
    L.x = __bfloat16_as_ushort(__float2bfloat16(v.x - __bfloat162float(h0)));
    L.y = __bfloat16_as_ushort(__float2bfloat16(v.y - __bfloat162float(h1)));
    L.z = __bfloat16_as_ushort(__float2bfloat16(v.z - __bfloat162float(h2)));
    L.w = __bfloat16_as_ushort(__float2bfloat16(v.w - __bfloat162float(h3)));
    ((ushort4*)hi)[i] = H;
    ((ushort4*)lo)[i] = L;
}

// ===========================================================================
// bf16 transpose of v hi/lo:  vt[b][h][d][j] = v[b*S+j][h*64+d]
// ===========================================================================
__global__ __launch_bounds__(256) void transpose_v_kernel(
    const __nv_bfloat16* __restrict__ vh, const __nv_bfloat16* __restrict__ vl,
    __nv_bfloat16* __restrict__ vth, __nv_bfloat16* __restrict__ vtl)
{
    __shared__ uint16_t th[64][72];
    __shared__ uint16_t tl[64][72];
    const int bh = blockIdx.y;
    const int b  = bh >> 4;
    const int h  = bh & 15;
    const int j0 = blockIdx.x * 64;
    const int tid = threadIdx.x;

#pragma unroll
    for (int i = 0; i < 4; i++) {
        int idx = tid + i * 256;          // 0..1023
        int j   = idx >> 4;               // 0..63
        int dq  = (idx & 15) * 4;         // 0..60
        size_t off = (size_t)(b * SEQ + j0 + j) * DM + h * HDIM + dq;
        ushort4 a = *(const ushort4*)((const uint16_t*)vh + off);
        ushort4 c = *(const ushort4*)((const uint16_t*)vl + off);
        th[dq + 0][j] = a.x; th[dq + 1][j] = a.y; th[dq + 2][j] = a.z; th[dq + 3][j] = a.w;
        tl[dq + 0][j] = c.x; tl[dq + 1][j] = c.y; tl[dq + 2][j] = c.z; tl[dq + 3][j] = c.w;
    }
    __syncthreads();

    const int d  = tid >> 2;              // 0..63
    const int jq = (tid & 3) * 16;        // 0..48
    uint16_t* oh = (uint16_t*)vth + ((size_t)bh * HDIM + d) * SEQ + j0 + jq;
    uint16_t* ol = (uint16_t*)vtl + ((size_t)bh * HDIM + d) * SEQ + j0 + jq;
#pragma unroll
    for (int c = 0; c < 4; c++) {
        ushort4 A, B;
        A.x = th[d][jq + c * 4 + 0]; A.y = th[d][jq + c * 4 + 1];
        A.z = th[d][jq + c * 4 + 2]; A.w = th[d][jq + c * 4 + 3];
        B.x = tl[d][jq + c * 4 + 0]; B.y = tl[d][jq + c * 4 + 1];
        B.z = tl[d][jq + c * 4 + 2]; B.w = tl[d][jq + c * 4 + 3];
        *(ushort4*)(oh + c * 4) = A;
        *(ushort4*)(ol + c * 4) = B;
    }
}

// ===========================================================================
// Generic bf16x3 compensated GEMM, ldmatrix fragments, cp.async 2-stage.
//   result = scale * (A @ W^T) (+ bias)
// SPLIT_OUT: write bf16 hi/lo (Ch, Cl); else fp32 C.
// ===========================================================================
#define SMM_STRIDE 40   // 32 k elems + 8 pad (bf16)

template <int NT, bool SPLIT_OUT>
__global__ __launch_bounds__(256) void mm3_kernel(
    const __nv_bfloat16* __restrict__ Ah, const __nv_bfloat16* __restrict__ Al,
    size_t asb, size_t ash, int lda,
    const __nv_bfloat16* __restrict__ Wh, const __nv_bfloat16* __restrict__ Wl,
    size_t wsb, size_t wsh, int ldw,
    const float* __restrict__ bias,
    float* __restrict__ C, __nv_bfloat16* __restrict__ Ch, __nv_bfloat16* __restrict__ Cl,
    size_t csb, size_t csh, int ldc,
    int K, float scale)
{
    constexpr int NATOMS  = NT / 16;
    constexpr int A_BYTES = 128 * SMM_STRIDE * 2;
    constexpr int W_BYTES = NT * SMM_STRIDE * 2;
    constexpr int STAGE   = 2 * A_BYTES + 2 * W_BYTES;

    extern __shared__ char smem[];
    const uint32_t sbase = smem_u32(smem);

    const int tid  = threadIdx.x;
    const int wid  = tid >> 5;
    const int lane = tid & 31;
    const int gid  = lane >> 2;
    const int tig  = lane & 3;
    const int wm   = wid & 3;
    const int wn   = wid >> 2;
    const int m0   = blockIdx.y * 128;
    const int n0   = blockIdx.x * NT;
    const int z    = blockIdx.z;
    const int zb   = z >> 4;
    const int zh   = z & 15;

    const __nv_bfloat16* pAh = Ah + (size_t)zb * asb + (size_t)zh * ash;
    const __nv_bfloat16* pAl = Al + (size_t)zb * asb + (size_t)zh * ash;
    const __nv_bfloat16* pWh = Wh + (size_t)zb * wsb + (size_t)zh * wsh;
    const __nv_bfloat16* pWl = Wl + (size_t)zb * wsb + (size_t)zh * wsh;

    // ldmatrix lane-address components
    const int a_r = lane & 15;              // row within 16
    const int a_c = (lane >> 4) << 3;       // 0 / 8 (k halfwords)
    const int w_r = (lane & 7) + ((lane & 16) >> 1);   // row within 16
    const int w_c = ((lane >> 3) & 1) << 3; // 0 / 8

    float acc[2][NATOMS][4];
#pragma unroll
    for (int i = 0; i < 2; i++)
#pragma unroll
        for (int j = 0; j < NATOMS; j++)
#pragma unroll
            for (int c = 0; c < 4; c++) acc[i][j][c] = 0.f;

    const int nk = K >> 5;

    auto load_stage = [&](int s, int k0) {
        uint32_t st = sbase + s * STAGE;
#pragma unroll
        for (int i = 0; i < 2; i++) {
            int idx = tid + i * 256;
            int row = idx >> 2;
            int kq  = idx & 3;
            uint32_t doff = (row * SMM_STRIDE + kq * 8) * 2;
            cp16(st + doff,           pAh + (size_t)(m0 + row) * lda + k0 + kq * 8);
            cp16(st + A_BYTES + doff, pAl + (size_t)(m0 + row) * lda + k0 + kq * 8);
        }
#pragma unroll
        for (int i = 0; i < (NT == 128 ? 2 : 1); i++) {
            int idx = tid + i * 256;
            int row = idx >> 2;
            int kq  = idx & 3;
            uint32_t doff = (row * SMM_STRIDE + kq * 8) * 2;
            cp16(st + 2 * A_BYTES + doff,           pWh + (size_t)(n0 + row) * ldw + k0 + kq * 8);
            cp16(st + 2 * A_BYTES + W_BYTES + doff, pWl + (size_t)(n0 + row) * ldw + k0 + kq * 8);
        }
    };

    load_stage(0, 0);
    cp_commit();

    for (int c0 = 0; c0 < nk; c0++) {
        if (c0 + 1 < nk) { load_stage((c0 + 1) & 1, (c0 + 1) * 32); cp_commit(); cp_wait<1>(); }
        else             { cp_wait<0>(); }
        __syncthreads();

        uint32_t st  = sbase + (c0 & 1) * STAGE;
        uint32_t sAh = st;
        uint32_t sAl = st + A_BYTES;
        uint32_t sWh = st + 2 * A_BYTES;
        uint32_t sWl = st + 2 * A_BYTES + W_BYTES;

#pragma unroll
        for (int ks = 0; ks < 2; ks++) {
            const int cb = ks * 16;   // k halfword base
            uint32_t afh[2][4], afl[2][4], wf[NATOMS][2];

            // A-hi fragments via ldmatrix.x4
#pragma unroll
            for (int i = 0; i < 2; i++) {
                int r = wm * 32 + i * 16 + a_r;
                ldsm_x4(afh[i], sAh + (r * SMM_STRIDE + cb + a_c) * 2);
            }
            // W-hi fragments: one x4 covers 2 n-atoms
#pragma unroll
            for (int jp = 0; jp < NATOMS / 2; jp++) {
                int n = wn * (NT / 2) + jp * 16 + w_r;
                ldsm_x4(&wf[2 * jp][0], sWh + (n * SMM_STRIDE + cb + w_c) * 2);
            }
#pragma unroll
            for (int i = 0; i < 2; i++)
#pragma unroll
                for (int j = 0; j < NATOMS; j++) mma16816(acc[i][j], afh[i], wf[j]);

            // A-lo fragments
#pragma unroll
            for (int i = 0; i < 2; i++) {
                int r = wm * 32 + i * 16 + a_r;
                ldsm_x4(afl[i], sAl + (r * SMM_STRIDE + cb + a_c) * 2);
            }
#pragma unroll
            for (int i = 0; i < 2; i++)
#pragma unroll
                for (int j = 0; j < NATOMS; j++) mma16816(acc[i][j], afl[i], wf[j]);

            // W-lo fragments (reuse wf)
#pragma unroll
            for (int jp = 0; jp < NATOMS / 2; jp++) {
                int n = wn * (NT / 2) + jp * 16 + w_r;
                ldsm_x4(&wf[2 * jp][0], sWl + (n * SMM_STRIDE + cb + w_c) * 2);
            }
#pragma unroll
            for (int i = 0; i < 2; i++)
#pragma unroll
                for (int j = 0; j < NATOMS; j++) mma16816(acc[i][j], afh[i], wf[j]);
        }
        __syncthreads();
    }

    // ---- epilogue ----
#pragma unroll
    for (int i = 0; i < 2; i++) {
        int row = m0 + wm * 32 + i * 16 + gid;
#pragma unroll
        for (int j = 0; j < NATOMS; j++) {
            int col = n0 + wn * (NT / 2) + j * 8 + tig * 2;
            float b0 = bias ? bias[col] : 0.f;
            float b1 = bias ? bias[col + 1] : 0.f;
            float f0 = acc[i][j][0] * scale + b0;
            float f1 = acc[i][j][1] * scale + b1;
            float f2 = acc[i][j][2] * scale + b0;
            float f3 = acc[i][j][3] * scale + b1;
            if (SPLIT_OUT) {
                uint16_t* pH = (uint16_t*)Ch + (size_t)zb * csb + (size_t)zh * csh;
                uint16_t* pL = (uint16_t*)Cl + (size_t)zb * csb + (size_t)zh * csh;
                __nv_bfloat16 h0 = __float2bfloat16(f0), h1 = __float2bfloat16(f1);
                __nv_bfloat16 h2 = __float2bfloat16(f2), h3 = __float2bfloat16(f3);
                ushort2 H0 = {__bfloat16_as_ushort(h0), __bfloat16_as_ushort(h1)};
                ushort2 H1 = {__bfloat16_as_ushort(h2), __bfloat16_as_ushort(h3)};
                ushort2 L0 = {__bfloat16_as_ushort(__float2bfloat16(f0 - __bfloat162float(h0))),
                              __bfloat16_as_ushort(__float2bfloat16(f1 - __bfloat162float(h1)))};
                ushort2 L1 = {__bfloat16_as_ushort(__float2bfloat16(f2 - __bfloat162float(h2))),
                              __bfloat16_as_ushort(__float2bfloat16(f3 - __bfloat162float(h3)))};
                *(ushort2*)(pH + (size_t)row * ldc + col) = H0;
                *(ushort2*)(pH + (size_t)(row + 8) * ldc + col) = H1;
                *(ushort2*)(pL + (size_t)row * ldc + col) = L0;
                *(ushort2*)(pL + (size_t)(row + 8) * ldc + col) = L1;
            } else {
                float* pC = C + (size_t)zb * csb + (size_t)zh * csh;
                *(float2*)(pC + (size_t)row * ldc + col) = make_float2(f0, f1);
                *(float2*)(pC + (size_t)(row + 8) * ldc + col) = make_float2(f2, f3);
            }
        }
    }
}

// ===========================================================================
// Softmax over j (+mask), NaN->0, sum over batch; emits bf16 hi/lo att.
// ===========================================================================
__global__ __launch_bounds__(256) void softmax_sum_kernel(
    const float* __restrict__ s, const float* __restrict__ mask,
    __nv_bfloat16* __restrict__ atth, __nv_bfloat16* __restrict__ attl)
{
    __shared__ float red[8];

    const int h   = blockIdx.x >> 10;
    const int qi  = blockIdx.x & 1023;
    const int tid = threadIdx.x;
    const int lane = tid & 31;
    const int warp = tid >> 5;

    float mv[4];
#pragma unroll
    for (int u = 0; u < 4; u++) mv[u] = mask[(size_t)qi * SEQ + tid + u * 256];

    float facc[4] = {0.f, 0.f, 0.f, 0.f};

    for (int b = 0; b < NB; b++) {
        const float* srow = s + (((size_t)(b * NHEAD + h)) * SEQ + qi) * SEQ;
        float rv[4];
        float m = -INFINITY;
#pragma unroll
        for (int u = 0; u < 4; u++) {
            rv[u] = srow[tid + u * 256] + mv[u];
            m = fmaxf(m, rv[u]);
        }
#pragma unroll
        for (int o = 16; o > 0; o >>= 1) m = fmaxf(m, __shfl_xor_sync(0xffffffffu, m, o));
        __syncthreads();
        if (lane == 0) red[warp] = m;
        __syncthreads();
        m = red[0];
#pragma unroll
        for (int w = 1; w < 8; w++) m = fmaxf(m, red[w]);

        float ssum = 0.f;
#pragma unroll
        for (int u = 0; u < 4; u++) {
            rv[u] = __expf(rv[u] - m);
            ssum += rv[u];
        }
#pragma unroll
        for (int o = 16; o > 0; o >>= 1) ssum += __shfl_xor_sync(0xffffffffu, ssum, o);
        __syncthreads();
        if (lane == 0) red[warp] = ssum;
        __syncthreads();
        ssum = 0.f;
#pragma unroll
        for (int w = 0; w < 8; w++) ssum += red[w];

        if (ssum > 0.f && isfinite(ssum)) {
            float inv = 1.f / ssum;
#pragma unroll
            for (int u = 0; u < 4; u++) facc[u] += rv[u] * inv;
        }
    }

    size_t rowoff = ((size_t)h * SEQ + qi) * SEQ;
#pragma unroll
    for (int u = 0; u < 4; u++) {
        float f = facc[u];
        __nv_bfloat16 hi = __float2bfloat16(f);
        atth[rowoff + tid + u * 256] = hi;
        attl[rowoff + tid + u * 256] = __float2bfloat16(f - __bfloat162float(hi));
    }
}

// ===========================================================================
extern "C" void kernel_launch(void* const* d_in, const int* in_sizes, int n_in,
                              void* d_out, int out_size)
{
    const float* x    = (const float*)d_in[0];
    const float* y    = (const float*)d_in[1];
    const float* mask = (const float*)d_in[2];
    const float* Wq   = (const float*)d_in[3];
    const float* bq   = (const float*)d_in[4];
    const float* Wk   = (const float*)d_in[5];
    const float* bk   = (const float*)d_in[6];
    const float* Wv   = (const float*)d_in[7];
    const float* bv   = (const float*)d_in[8];
    const float* Wo   = (const float*)d_in[9];
    const float* bo   = (const float*)d_in[10];
    float* out = (float*)d_out;

    float* sc;
    cudaGetSymbolAddress((void**)&sc, g_s);

    __nv_bfloat16 *yh, *yl, *xh, *xl, *qh, *ql, *kh, *kl, *vh, *vl;
    __nv_bfloat16 *vth, *vtl, *avh, *avl, *atth, *attl;
    __nv_bfloat16 *wqh, *wql, *wkh, *wkl, *wvh, *wvl, *woh, *wol;
    cudaGetSymbolAddress((void**)&yh, g_yh);   cudaGetSymbolAddress((void**)&yl, g_yl);
    cudaGetSymbolAddress((void**)&xh, g_xh);   cudaGetSymbolAddress((void**)&xl, g_xl);
    cudaGetSymbolAddress((void**)&qh, g_qh);   cudaGetSymbolAddress((void**)&ql, g_ql);
    cudaGetSymbolAddress((void**)&kh, g_kh);   cudaGetSymbolAddress((void**)&kl, g_kl);
    cudaGetSymbolAddress((void**)&vh, g_vh);   cudaGetSymbolAddress((void**)&vl, g_vl);
    cudaGetSymbolAddress((void**)&vth, g_vth); cudaGetSymbolAddress((void**)&vtl, g_vtl);
    cudaGetSymbolAddress((void**)&avh, g_avh); cudaGetSymbolAddress((void**)&avl, g_avl);
    cudaGetSymbolAddress((void**)&atth, g_atth); cudaGetSymbolAddress((void**)&attl, g_attl);
    cudaGetSymbolAddress((void**)&wqh, g_wqh); cudaGetSymbolAddress((void**)&wql, g_wql);
    cudaGetSymbolAddress((void**)&wkh, g_wkh); cudaGetSymbolAddress((void**)&wkl, g_wkl);
    cudaGetSymbolAddress((void**)&wvh, g_wvh); cudaGetSymbolAddress((void**)&wvl, g_wvl);
    cudaGetSymbolAddress((void**)&woh, g_woh); cudaGetSymbolAddress((void**)&wol, g_wol);

    constexpr int SMEM128 = 2 * (2 * 128 * SMM_STRIDE * 2 + 2 * 128 * SMM_STRIDE * 2); // 81920
    constexpr int SMEM64  = 2 * (2 * 128 * SMM_STRIDE * 2 + 2 * 64 * SMM_STRIDE * 2);  // 61440
    cudaFuncSetAttribute(mm3_kernel<128, true>,  cudaFuncAttributeMaxDynamicSharedMemorySize, SMEM128);
    cudaFuncSetAttribute(mm3_kernel<128, false>, cudaFuncAttributeMaxDynamicSharedMemorySize, SMEM128);
    cudaFuncSetAttribute(mm3_kernel<64, true>,   cudaFuncAttributeMaxDynamicSharedMemorySize, SMEM64);

    const size_t SDM = (size_t)SEQ * DM;
    const size_t SS  = (size_t)SEQ * SEQ;

    // ---- input splits (1 launch) ----
    split6_kernel<<<dim3(MR * DM / 4 / 256, 6), 256>>>(
        y, yh, yl, x, xh, xl,
        Wq, wqh, wql, Wk, wkh, wkl, Wv, wvh, wvl, Wo, woh, wol);

    // ---- projections: split bf16 outputs directly ----
    dim3 pgrid(DM / 128, MR / 128, 1);
    mm3_kernel<128, true><<<pgrid, 256, SMEM128>>>(
        yh, yl, 0, 0, DM, wqh, wql, 0, 0, DM,
        bq, nullptr, qh, ql, 0, 0, DM, DM, 1.f);
    mm3_kernel<128, true><<<pgrid, 256, SMEM128>>>(
        xh, xl, 0, 0, DM, wkh, wkl, 0, 0, DM,
        bk, nullptr, kh, kl, 0, 0, DM, DM, 1.f);
    mm3_kernel<128, true><<<pgrid, 256, SMEM128>>>(
        xh, xl, 0, 0, DM, wvh, wvl, 0, 0, DM,
        bv, nullptr, vh, vl, 0, 0, DM, DM, 1.f);

    // ---- v transpose (bf16) ----
    transpose_v_kernel<<<dim3(SEQ / 64, NB * NHEAD), 256>>>(vh, vl, vth, vtl);

    // ---- scores: s[b,h] = 0.125 * q_bh @ k_bh^T  (K=64) ----
    mm3_kernel<128, false><<<dim3(SEQ / 128, SEQ / 128, NB * NHEAD), 256, SMEM128>>>(
        qh, ql, SDM, (size_t)HDIM, DM,
        kh, kl, SDM, (size_t)HDIM, DM,
        nullptr, sc, nullptr, nullptr, (size_t)NHEAD * SS, SS, SEQ, HDIM, 0.125f);

    // ---- softmax + batch-sum -> bf16 hi/lo att ----
    softmax_sum_kernel<<<NHEAD * SEQ, 256>>>(sc, mask, atth, attl);

    // ---- AV: av[b,:,h*64+d] = att_h @ vt_bh^T  (N=64, K=1024), split out ----
    mm3_kernel<64, true><<<dim3(1, SEQ / 128, NB * NHEAD), 256, SMEM64>>>(
        atth, attl, 0, SS, SEQ,
        vth, vtl, (size_t)NHEAD * HDIM * SEQ, (size_t)HDIM * SEQ, SEQ,
        nullptr, nullptr, avh, avl, SDM, (size_t)HDIM, DM, SEQ, 1.f);

    // ---- output projection (fp32 out + bias) ----
    mm3_kernel<128, false><<<pgrid, 256, SMEM128>>>(
        avh, avl, 0, 0, DM, woh, wol, 0, 0, DM,
        bo, out, nullptr, nullptr, 0, 0, DM, DM, 1.f);
}

// round 11
// speedup vs baseline: 1.5346x; 1.5346x over previous
#include <cuda_runtime.h>
#include <cuda_bf16.h>
#include <math.h>
#include <stdint.h>

// Problem constants
constexpr int SEQ   = 1024;
constexpr int DM    = 1024;
constexpr int NHEAD = 16;
constexpr int HDIM  = 64;
constexpr int NB    = 4;
constexpr int MR    = NB * SEQ;

// ---------------- scratch (device globals; no allocation allowed) ----------
__device__ float g_s [(size_t)NB * NHEAD * SEQ * SEQ];   // raw scores (b,h,q,j)

__device__ __nv_bfloat16 g_yh[(size_t)MR * DM];
__device__ __nv_bfloat16 g_yl[(size_t)MR * DM];
__device__ __nv_bfloat16 g_xh[(size_t)MR * DM];
__device__ __nv_bfloat16 g_xl[(size_t)MR * DM];
__device__ __nv_bfloat16 g_qh[(size_t)MR * DM];
__device__ __nv_bfloat16 g_ql[(size_t)MR * DM];
__device__ __nv_bfloat16 g_kh[(size_t)MR * DM];
__device__ __nv_bfloat16 g_kl[(size_t)MR * DM];
__device__ __nv_bfloat16 g_vh[(size_t)MR * DM];
__device__ __nv_bfloat16 g_vl[(size_t)MR * DM];
__device__ __nv_bfloat16 g_vth[(size_t)MR * DM];   // v^T per (b,h): [b][h][d][j]
__device__ __nv_bfloat16 g_vtl[(size_t)MR * DM];
__device__ __nv_bfloat16 g_avh[(size_t)MR * DM];
__device__ __nv_bfloat16 g_avl[(size_t)MR * DM];
__device__ __nv_bfloat16 g_atth[(size_t)NHEAD * SEQ * SEQ];
__device__ __nv_bfloat16 g_attl[(size_t)NHEAD * SEQ * SEQ];
__device__ __nv_bfloat16 g_wqh[(size_t)DM * DM];
__device__ __nv_bfloat16 g_wql[(size_t)DM * DM];
__device__ __nv_bfloat16 g_wkh[(size_t)DM * DM];
__device__ __nv_bfloat16 g_wkl[(size_t)DM * DM];
__device__ __nv_bfloat16 g_wvh[(size_t)DM * DM];
__device__ __nv_bfloat16 g_wvl[(size_t)DM * DM];
__device__ __nv_bfloat16 g_woh[(size_t)DM * DM];
__device__ __nv_bfloat16 g_wol[(size_t)DM * DM];

// ===========================================================================
// helpers
// ===========================================================================
__device__ __forceinline__ uint32_t smem_u32(const void* p) {
    uint32_t r;
    asm("{ .reg .u64 t; cvta.to.shared.u64 t, %1; cvt.u32.u64 %0, t; }"
        : "=r"(r) : "l"(p));
    return r;
}
__device__ __forceinline__ void cp16(uint32_t dst, const void* src) {
    asm volatile("cp.async.cg.shared.global [%0], [%1], 16;" :: "r"(dst), "l"(src));
}
__device__ __forceinline__ void cp_commit() {
    asm volatile("cp.async.commit_group;" ::: "memory");
}
template <int N>
__device__ __forceinline__ void cp_wait() {
    asm volatile("cp.async.wait_group %0;" :: "n"(N) : "memory");
}
__device__ __forceinline__ void ldsm_x4(uint32_t* r, uint32_t addr) {
    asm volatile("ldmatrix.sync.aligned.m8n8.x4.shared.b16 {%0,%1,%2,%3}, [%4];"
        : "=r"(r[0]), "=r"(r[1]), "=r"(r[2]), "=r"(r[3]) : "r"(addr));
}
__device__ __forceinline__ void mma16816(
    float* d, const uint32_t* a, const uint32_t* b)
{
    asm volatile(
        "mma.sync.aligned.m16n8k16.row.col.f32.bf16.bf16.f32 "
        "{%0,%1,%2,%3}, {%4,%5,%6,%7}, {%8,%9}, {%0,%1,%2,%3};"
        : "+f"(d[0]), "+f"(d[1]), "+f"(d[2]), "+f"(d[3])
        : "r"(a[0]), "r"(a[1]), "r"(a[2]), "r"(a[3]), "r"(b[0]), "r"(b[1]));
}

// ===========================================================================
// combined fp32 -> bf16 hi/lo split for the 6 input tensors (1 launch)
// ===========================================================================
__global__ __launch_bounds__(256) void split6_kernel(
    const float* __restrict__ y,  __nv_bfloat16* yh, __nv_bfloat16* yl,
    const float* __restrict__ x,  __nv_bfloat16* xh, __nv_bfloat16* xl,
    const float* __restrict__ wq, __nv_bfloat16* qh, __nv_bfloat16* ql,
    const float* __restrict__ wk, __nv_bfloat16* kh, __nv_bfloat16* kl,
    const float* __restrict__ wv, __nv_bfloat16* vh, __nv_bfloat16* vl,
    const float* __restrict__ wo, __nv_bfloat16* oh, __nv_bfloat16* ol)
{
    const int seg = blockIdx.y;
    const float* in; __nv_bfloat16 *hi, *lo; int n4;
    switch (seg) {
        case 0:  in = y;  hi = yh; lo = yl; n4 = MR * DM / 4; break;
        case 1:  in = x;  hi = xh; lo = xl; n4 = MR * DM / 4; break;
        case 2:  in = wq; hi = qh; lo = ql; n4 = DM * DM / 4; break;
        case 3:  in = wk; hi = kh; lo = kl; n4 = DM * DM / 4; break;
        case 4:  in = wv; hi = vh; lo = vl; n4 = DM * DM / 4; break;
        default: in = wo; hi = oh; lo = ol; n4 = DM * DM / 4; break;
    }
    int i = blockIdx.x * blockDim.x + threadIdx.x;
    if (i >= n4) return;
    float4 v = ((const float4*)in)[i];
    __nv_bfloat16 h0 = __float2bfloat16(v.x);
    __nv_bfloat16 h1 = __float2bfloat16(v.y);
    __nv_bfloat16 h2 = __float2bfloat16(v.z);
    __nv_bfloat16 h3 = __float2bfloat16(v.w);
    ushort4 H, L;
    H.x = __bfloat16_as_ushort(h0); H.y = __bfloat16_as_ushort(h1);
    H.z = __bfloat16_as_ushort(h2); H.w = __bfloat16_as_ushort(h3);
    L.x = __bfloat16_as_ushort(__float2bfloat16(v.x - __bfloat162float(h0)));
    L.y = __bfloat16_as_ushort(__float2bfloat16(v.y - __bfloat162float(h1)));
    L.z = __bfloat16_as_ushort(__float2bfloat16(v.z - __bfloat162float(h2)));
    L.w = __bfloat16_as_ushort(__float2bfloat16(v.w - __bfloat162float(h3)));
    ((ushort4*)hi)[i] = H;
    ((ushort4*)lo)[i] = L;
}

// ===========================================================================
// bf16 transpose of v hi/lo:  vt[b][h][d][j] = v[b*S+j][h*64+d]
// ===========================================================================
__global__ __launch_bounds__(256) void transpose_v_kernel(
    const __nv_bfloat16* __restrict__ vh, const __nv_bfloat16* __restrict__ vl,
    __nv_bfloat16* __restrict__ vth, __nv_bfloat16* __restrict__ vtl)
{
    __shared__ uint16_t th[64][72];
    __shared__ uint16_t tl[64][72];
    const int bh = blockIdx.y;
    const int b  = bh >> 4;
    const int h  = bh & 15;
    const int j0 = blockIdx.x * 64;
    const int tid = threadIdx.x;

#pragma unroll
    for (int i = 0; i < 4; i++) {
        int idx = tid + i * 256;          // 0..1023
        int j   = idx >> 4;               // 0..63
        int dq  = (idx & 15) * 4;         // 0..60
        size_t off = (size_t)(b * SEQ + j0 + j) * DM + h * HDIM + dq;
        ushort4 a = *(const ushort4*)((const uint16_t*)vh + off);
        ushort4 c = *(const ushort4*)((const uint16_t*)vl + off);
        th[dq + 0][j] = a.x; th[dq + 1][j] = a.y; th[dq + 2][j] = a.z; th[dq + 3][j] = a.w;
        tl[dq + 0][j] = c.x; tl[dq + 1][j] = c.y; tl[dq + 2][j] = c.z; tl[dq + 3][j] = c.w;
    }
    __syncthreads();

    const int d  = tid >> 2;              // 0..63
    const int jq = (tid & 3) * 16;        // 0..48
    uint16_t* oh = (uint16_t*)vth + ((size_t)bh * HDIM + d) * SEQ + j0 + jq;
    uint16_t* ol = (uint16_t*)vtl + ((size_t)bh * HDIM + d) * SEQ + j0 + jq;
#pragma unroll
    for (int c = 0; c < 4; c++) {
        ushort4 A, B;
        A.x = th[d][jq + c * 4 + 0]; A.y = th[d][jq + c * 4 + 1];
        A.z = th[d][jq + c * 4 + 2]; A.w = th[d][jq + c * 4 + 3];
        B.x = tl[d][jq + c * 4 + 0]; B.y = tl[d][jq + c * 4 + 1];
        B.z = tl[d][jq + c * 4 + 2]; B.w = tl[d][jq + c * 4 + 3];
        *(ushort4*)(oh + c * 4) = A;
        *(ushort4*)(ol + c * 4) = B;
    }
}

// ===========================================================================
// Generic bf16x3 compensated GEMM, ldmatrix fragments, cp.async 2-stage.
//   result = scale * (A @ W^T) (+ bias)
// SPLIT_OUT: write bf16 hi/lo (Ch, Cl); else fp32 C.
// __launch_bounds__(256, 2): force 2-CTA/SM residency (reg cap ~126).
// ===========================================================================
#define SMM_STRIDE 40   // 32 k elems + 8 pad (bf16)

template <int NT, bool SPLIT_OUT>
__global__ __launch_bounds__(256, 2) void mm3_kernel(
    const __nv_bfloat16* __restrict__ Ah, const __nv_bfloat16* __restrict__ Al,
    size_t asb, size_t ash, int lda,
    const __nv_bfloat16* __restrict__ Wh, const __nv_bfloat16* __restrict__ Wl,
    size_t wsb, size_t wsh, int ldw,
    const float* __restrict__ bias,
    float* __restrict__ C, __nv_bfloat16* __restrict__ Ch, __nv_bfloat16* __restrict__ Cl,
    size_t csb, size_t csh, int ldc,
    int K, float scale)
{
    constexpr int NATOMS  = NT / 16;
    constexpr int A_BYTES = 128 * SMM_STRIDE * 2;
    constexpr int W_BYTES = NT * SMM_STRIDE * 2;
    constexpr int STAGE   = 2 * A_BYTES + 2 * W_BYTES;

    extern __shared__ char smem[];
    const uint32_t sbase = smem_u32(smem);

    const int tid  = threadIdx.x;
    const int wid  = tid >> 5;
    const int lane = tid & 31;
    const int gid  = lane >> 2;
    const int tig  = lane & 3;
    const int wm   = wid & 3;
    const int wn   = wid >> 2;
    const int m0   = blockIdx.y * 128;
    const int n0   = blockIdx.x * NT;
    const int z    = blockIdx.z;
    const int zb   = z >> 4;
    const int zh   = z & 15;

    const __nv_bfloat16* pAh = Ah + (size_t)zb * asb + (size_t)zh * ash;
    const __nv_bfloat16* pAl = Al + (size_t)zb * asb + (size_t)zh * ash;
    const __nv_bfloat16* pWh = Wh + (size_t)zb * wsb + (size_t)zh * wsh;
    const __nv_bfloat16* pWl = Wl + (size_t)zb * wsb + (size_t)zh * wsh;

    // ldmatrix lane-address components
    const int a_r = lane & 15;              // row within 16
    const int a_c = (lane >> 4) << 3;       // 0 / 8 (k halfwords)
    const int w_r = (lane & 7) + ((lane & 16) >> 1);   // row within 16
    const int w_c = ((lane >> 3) & 1) << 3; // 0 / 8

    float acc[2][NATOMS][4];
#pragma unroll
    for (int i = 0; i < 2; i++)
#pragma unroll
        for (int j = 0; j < NATOMS; j++)
#pragma unroll
            for (int c = 0; c < 4; c++) acc[i][j][c] = 0.f;

    const int nk = K >> 5;

    auto load_stage = [&](int s, int k0) {
        uint32_t st = sbase + s * STAGE;
#pragma unroll
        for (int i = 0; i < 2; i++) {
            int idx = tid + i * 256;
            int row = idx >> 2;
            int kq  = idx & 3;
            uint32_t doff = (row * SMM_STRIDE + kq * 8) * 2;
            cp16(st + doff,           pAh + (size_t)(m0 + row) * lda + k0 + kq * 8);
            cp16(st + A_BYTES + doff, pAl + (size_t)(m0 + row) * lda + k0 + kq * 8);
        }
#pragma unroll
        for (int i = 0; i < (NT == 128 ? 2 : 1); i++) {
            int idx = tid + i * 256;
            int row = idx >> 2;
            int kq  = idx & 3;
            uint32_t doff = (row * SMM_STRIDE + kq * 8) * 2;
            cp16(st + 2 * A_BYTES + doff,           pWh + (size_t)(n0 + row) * ldw + k0 + kq * 8);
            cp16(st + 2 * A_BYTES + W_BYTES + doff, pWl + (size_t)(n0 + row) * ldw + k0 + kq * 8);
        }
    };

    load_stage(0, 0);
    cp_commit();

    for (int c0 = 0; c0 < nk; c0++) {
        if (c0 + 1 < nk) { load_stage((c0 + 1) & 1, (c0 + 1) * 32); cp_commit(); cp_wait<1>(); }
        else             { cp_wait<0>(); }
        __syncthreads();

        uint32_t st  = sbase + (c0 & 1) * STAGE;
        uint32_t sAh = st;
        uint32_t sAl = st + A_BYTES;
        uint32_t sWh = st + 2 * A_BYTES;
        uint32_t sWl = st + 2 * A_BYTES + W_BYTES;

#pragma unroll
        for (int ks = 0; ks < 2; ks++) {
            const int cb = ks * 16;   // k halfword base
            uint32_t afh[2][4], afl[2][4], wf[NATOMS][2];

            // A-hi fragments via ldmatrix.x4
#pragma unroll
            for (int i = 0; i < 2; i++) {
                int r = wm * 32 + i * 16 + a_r;
                ldsm_x4(afh[i], sAh + (r * SMM_STRIDE + cb + a_c) * 2);
            }
            // W-hi fragments: one x4 covers 2 n-atoms
#pragma unroll
            for (int jp = 0; jp < NATOMS / 2; jp++) {
                int n = wn * (NT / 2) + jp * 16 + w_r;
                ldsm_x4(&wf[2 * jp][0], sWh + (n * SMM_STRIDE + cb + w_c) * 2);
            }
#pragma unroll
            for (int i = 0; i < 2; i++)
#pragma unroll
                for (int j = 0; j < NATOMS; j++) mma16816(acc[i][j], afh[i], wf[j]);

            // A-lo fragments
#pragma unroll
            for (int i = 0; i < 2; i++) {
                int r = wm * 32 + i * 16 + a_r;
                ldsm_x4(afl[i], sAl + (r * SMM_STRIDE + cb + a_c) * 2);
            }
#pragma unroll
            for (int i = 0; i < 2; i++)
#pragma unroll
                for (int j = 0; j < NATOMS; j++) mma16816(acc[i][j], afl[i], wf[j]);

            // W-lo fragments (reuse wf)
#pragma unroll
            for (int jp = 0; jp < NATOMS / 2; jp++) {
                int n = wn * (NT / 2) + jp * 16 + w_r;
                ldsm_x4(&wf[2 * jp][0], sWl + (n * SMM_STRIDE + cb + w_c) * 2);
            }
#pragma unroll
            for (int i = 0; i < 2; i++)
#pragma unroll
                for (int j = 0; j < NATOMS; j++) mma16816(acc[i][j], afh[i], wf[j]);
        }
        __syncthreads();
    }

    // ---- epilogue ----
#pragma unroll
    for (int i = 0; i < 2; i++) {
        int row = m0 + wm * 32 + i * 16 + gid;
#pragma unroll
        for (int j = 0; j < NATOMS; j++) {
            int col = n0 + wn * (NT / 2) + j * 8 + tig * 2;
            float b0 = bias ? bias[col] : 0.f;
            float b1 = bias ? bias[col + 1] : 0.f;
            float f0 = acc[i][j][0] * scale + b0;
            float f1 = acc[i][j][1] * scale + b1;
            float f2 = acc[i][j][2] * scale + b0;
            float f3 = acc[i][j][3] * scale + b1;
            if (SPLIT_OUT) {
                uint16_t* pH = (uint16_t*)Ch + (size_t)zb * csb + (size_t)zh * csh;
                uint16_t* pL = (uint16_t*)Cl + (size_t)zb * csb + (size_t)zh * csh;
                __nv_bfloat16 h0 = __float2bfloat16(f0), h1 = __float2bfloat16(f1);
                __nv_bfloat16 h2 = __float2bfloat16(f2), h3 = __float2bfloat16(f3);
                ushort2 H0 = {__bfloat16_as_ushort(h0), __bfloat16_as_ushort(h1)};
                ushort2 H1 = {__bfloat16_as_ushort(h2), __bfloat16_as_ushort(h3)};
                ushort2 L0 = {__bfloat16_as_ushort(__float2bfloat16(f0 - __bfloat162float(h0))),
                              __bfloat16_as_ushort(__float2bfloat16(f1 - __bfloat162float(h1)))};
                ushort2 L1 = {__bfloat16_as_ushort(__float2bfloat16(f2 - __bfloat162float(h2))),
                              __bfloat16_as_ushort(__float2bfloat16(f3 - __bfloat162float(h3)))};
                *(ushort2*)(pH + (size_t)row * ldc + col) = H0;
                *(ushort2*)(pH + (size_t)(row + 8) * ldc + col) = H1;
                *(ushort2*)(pL + (size_t)row * ldc + col) = L0;
                *(ushort2*)(pL + (size_t)(row + 8) * ldc + col) = L1;
            } else {
                float* pC = C + (size_t)zb * csb + (size_t)zh * csh;
                *(float2*)(pC + (size_t)row * ldc + col) = make_float2(f0, f1);
                *(float2*)(pC + (size_t)(row + 8) * ldc + col) = make_float2(f2, f3);
            }
        }
    }
}

// ===========================================================================
// Softmax over j (+mask), NaN->0, sum over batch; emits bf16 hi/lo att.
// ===========================================================================
__global__ __launch_bounds__(256) void softmax_sum_kernel(
    const float* __restrict__ s, const float* __restrict__ mask,
    __nv_bfloat16* __restrict__ atth, __nv_bfloat16* __restrict__ attl)
{
    __shared__ float red[8];

    const int h   = blockIdx.x >> 10;
    const int qi  = blockIdx.x & 1023;
    const int tid = threadIdx.x;
    const int lane = tid & 31;
    const int warp = tid >> 5;

    float mv[4];
#pragma unroll
    for (int u = 0; u < 4; u++) mv[u] = mask[(size_t)qi * SEQ + tid + u * 256];

    float facc[4] = {0.f, 0.f, 0.f, 0.f};

    for (int b = 0; b < NB; b++) {
        const float* srow = s + (((size_t)(b * NHEAD + h)) * SEQ + qi) * SEQ;
        float rv[4];
        float m = -INFINITY;
#pragma unroll
        for (int u = 0; u < 4; u++) {
            rv[u] = srow[tid + u * 256] + mv[u];
            m = fmaxf(m, rv[u]);
        }
#pragma unroll
        for (int o = 16; o > 0; o >>= 1) m = fmaxf(m, __shfl_xor_sync(0xffffffffu, m, o));
        __syncthreads();
        if (lane == 0) red[warp] = m;
        __syncthreads();
        m = red[0];
#pragma unroll
        for (int w = 1; w < 8; w++) m = fmaxf(m, red[w]);

        float ssum = 0.f;
#pragma unroll
        for (int u = 0; u < 4; u++) {
            rv[u] = __expf(rv[u] - m);
            ssum += rv[u];
        }
#pragma unroll
        for (int o = 16; o > 0; o >>= 1) ssum += __shfl_xor_sync(0xffffffffu, ssum, o);
        __syncthreads();
        if (lane == 0) red[warp] = ssum;
        __syncthreads();
        ssum = 0.f;
#pragma unroll
        for (int w = 0; w < 8; w++) ssum += red[w];

        if (ssum > 0.f && isfinite(ssum)) {
            float inv = 1.f / ssum;
#pragma unroll
            for (int u = 0; u < 4; u++) facc[u] += rv[u] * inv;
        }
    }

    size_t rowoff = ((size_t)h * SEQ + qi) * SEQ;
#pragma unroll
    for (int u = 0; u < 4; u++) {
        float f = facc[u];
        __nv_bfloat16 hi = __float2bfloat16(f);
        atth[rowoff + tid + u * 256] = hi;
        attl[rowoff + tid + u * 256] = __float2bfloat16(f - __bfloat162float(hi));
    }
}

// ===========================================================================
extern "C" void kernel_launch(void* const* d_in, const int* in_sizes, int n_in,
                              void* d_out, int out_size)
{
    const float* x    = (const float*)d_in[0];
    const float* y    = (const float*)d_in[1];
    const float* mask = (const float*)d_in[2];
    const float* Wq   = (const float*)d_in[3];
    const float* bq   = (const float*)d_in[4];
    const float* Wk   = (const float*)d_in[5];
    const float* bk   = (const float*)d_in[6];
    const float* Wv   = (const float*)d_in[7];
    const float* bv   = (const float*)d_in[8];
    const float* Wo   = (const float*)d_in[9];
    const float* bo   = (const float*)d_in[10];
    float* out = (float*)d_out;

    float* sc;
    cudaGetSymbolAddress((void**)&sc, g_s);

    __nv_bfloat16 *yh, *yl, *xh, *xl, *qh, *ql, *kh, *kl, *vh, *vl;
    __nv_bfloat16 *vth, *vtl, *avh, *avl, *atth, *attl;
    __nv_bfloat16 *wqh, *wql, *wkh, *wkl, *wvh, *wvl, *woh, *wol;
    cudaGetSymbolAddress((void**)&yh, g_yh);   cudaGetSymbolAddress((void**)&yl, g_yl);
    cudaGetSymbolAddress((void**)&xh, g_xh);   cudaGetSymbolAddress((void**)&xl, g_xl);
    cudaGetSymbolAddress((void**)&qh, g_qh);   cudaGetSymbolAddress((void**)&ql, g_ql);
    cudaGetSymbolAddress((void**)&kh, g_kh);   cudaGetSymbolAddress((void**)&kl, g_kl);
    cudaGetSymbolAddress((void**)&vh, g_vh);   cudaGetSymbolAddress((void**)&vl, g_vl);
    cudaGetSymbolAddress((void**)&vth, g_vth); cudaGetSymbolAddress((void**)&vtl, g_vtl);
    cudaGetSymbolAddress((void**)&avh, g_avh); cudaGetSymbolAddress((void**)&avl, g_avl);
    cudaGetSymbolAddress((void**)&atth, g_atth); cudaGetSymbolAddress((void**)&attl, g_attl);
    cudaGetSymbolAddress((void**)&wqh, g_wqh); cudaGetSymbolAddress((void**)&wql, g_wql);
    cudaGetSymbolAddress((void**)&wkh, g_wkh); cudaGetSymbolAddress((void**)&wkl, g_wkl);
    cudaGetSymbolAddress((void**)&wvh, g_wvh); cudaGetSymbolAddress((void**)&wvl, g_wvl);
    cudaGetSymbolAddress((void**)&woh, g_woh); cudaGetSymbolAddress((void**)&wol, g_wol);

    constexpr int SMEM128 = 2 * (2 * 128 * SMM_STRIDE * 2 + 2 * 128 * SMM_STRIDE * 2); // 81920
    constexpr int SMEM64  = 2 * (2 * 128 * SMM_STRIDE * 2 + 2 * 64 * SMM_STRIDE * 2);  // 61440
    cudaFuncSetAttribute(mm3_kernel<128, true>,  cudaFuncAttributeMaxDynamicSharedMemorySize, SMEM128);
    cudaFuncSetAttribute(mm3_kernel<128, false>, cudaFuncAttributeMaxDynamicSharedMemorySize, SMEM128);
    cudaFuncSetAttribute(mm3_kernel<64, true>,   cudaFuncAttributeMaxDynamicSharedMemorySize, SMEM64);

    const size_t SDM = (size_t)SEQ * DM;
    const size_t SS  = (size_t)SEQ * SEQ;

    // ---- input splits (1 launch) ----
    split6_kernel<<<dim3(MR * DM / 4 / 256, 6), 256>>>(
        y, yh, yl, x, xh, xl,
        Wq, wqh, wql, Wk, wkh, wkl, Wv, wvh, wvl, Wo, woh, wol);

    // ---- projections: split bf16 outputs directly ----
    dim3 pgrid(DM / 128, MR / 128, 1);
    mm3_kernel<128, true><<<pgrid, 256, SMEM128>>>(
        yh, yl, 0, 0, DM, wqh, wql, 0, 0, DM,
        bq, nullptr, qh, ql, 0, 0, DM, DM, 1.f);
    mm3_kernel<128, true><<<pgrid, 256, SMEM128>>>(
        xh, xl, 0, 0, DM, wkh, wkl, 0, 0, DM,
        bk, nullptr, kh, kl, 0, 0, DM, DM, 1.f);
    mm3_kernel<128, true><<<pgrid, 256, SMEM128>>>(
        xh, xl, 0, 0, DM, wvh, wvl, 0, 0, DM,
        bv, nullptr, vh, vl, 0, 0, DM, DM, 1.f);

    // ---- v transpose (bf16) ----
    transpose_v_kernel<<<dim3(SEQ / 64, NB * NHEAD), 256>>>(vh, vl, vth, vtl);

    // ---- scores: s[b,h] = 0.125 * q_bh @ k_bh^T  (K=64) ----
    mm3_kernel<128, false><<<dim3(SEQ / 128, SEQ / 128, NB * NHEAD), 256, SMEM128>>>(
        qh, ql, SDM, (size_t)HDIM, DM,
        kh, kl, SDM, (size_t)HDIM, DM,
        nullptr, sc, nullptr, nullptr, (size_t)NHEAD * SS, SS, SEQ, HDIM, 0.125f);

    // ---- softmax + batch-sum -> bf16 hi/lo att ----
    softmax_sum_kernel<<<NHEAD * SEQ, 256>>>(sc, mask, atth, attl);

    // ---- AV: av[b,:,h*64+d] = att_h @ vt_bh^T  (N=64, K=1024), split out ----
    mm3_kernel<64, true><<<dim3(1, SEQ / 128, NB * NHEAD), 256, SMEM64>>>(
        atth, attl, 0, SS, SEQ,
        vth, vtl, (size_t)NHEAD * HDIM * SEQ, (size_t)HDIM * SEQ, SEQ,
        nullptr, nullptr, avh, avl, SDM, (size_t)HDIM, DM, SEQ, 1.f);

    // ---- output projection (fp32 out + bias) ----
    mm3_kernel<128, false><<<pgrid, 256, SMEM128>>>(
        avh, avl, 0, 0, DM, woh, wol, 0, 0, DM,
        bo, out, nullptr, nullptr, 0, 0, DM, DM, 1.f);
}